// round 2
// baseline (speedup 1.0000x reference)
#include <cuda_runtime.h>
#include <math.h>

#define NN 100000
#define FF 128
#define HH 16
#define CC 40
#define ALPHA 0.1f
#define BN_EPS 1e-5f

// ---------------- scratch (device globals; no allocation) ----------------
__device__ __align__(16) float g_tmps[NN * HH];   // (x@W1) * dinv  (src-side, conv1)
__device__ __align__(16) float g_agg1[NN * HH];   // conv1 sum, init = self-loop term
__device__ __align__(16) float g_agg2[NN * HH];   // conv2 sum, init = self-loop term
__device__ __align__(16) float g_h[NN * HH];      // post-relu hidden
__device__ __align__(16) float g_h2s[NN * HH];    // post-hops hidden * dinv (src-side, conv2)
__device__ float g_deg[NN];
__device__ float g_dinv[NN];
__device__ float g_stats[2 * HH];   // [sum | sumsq]
__device__ float g_scale[HH];
__device__ float g_shift[HH];

// ---------------- kernels ----------------

__global__ void k_init(int n) {
    int i = blockIdx.x * blockDim.x + threadIdx.x;
    if (i < n) g_deg[i] = 1.0f;          // self-loop
    if (i < 2 * HH) g_stats[i] = 0.0f;
}

__global__ void k_deg(const int* __restrict__ dst, int ne) {
    int e = blockIdx.x * blockDim.x + threadIdx.x;
    if (e < ne) atomicAdd(&g_deg[dst[e]], 1.0f);
}

__global__ void k_dinv(int n) {
    int i = blockIdx.x * blockDim.x + threadIdx.x;
    if (i < n) g_dinv[i] = rsqrtf(g_deg[i]);
}

// x[N,128] @ W1[128,16] * dinv[node] -> g_tmps AND g_agg1 (self-loop init).
// Warp-cooperative: 8 lanes per node, 4 nodes per warp. Fully coalesced:
// per LDG.128, warp touches 4 rows x 128B contiguous segments.
__global__ void k_mm1(const float* __restrict__ x, const float* __restrict__ W1, int n) {
    __shared__ float w1s[FF * HH];
    int t = threadIdx.x;                       // 256 threads = 8 warps = 32 nodes/block
    for (int i = t; i < FF * HH; i += blockDim.x) w1s[i] = W1[i];
    __syncthreads();

    int lane = t & 31;
    int sub  = lane >> 3;                      // node within warp (0..3)
    int li   = lane & 7;                       // lane within node group (0..7)
    int node = blockIdx.x * 32 + (t >> 5) * 4 + sub;
    if (node >= n) return;

    const float4* xp = (const float4*)(x + (size_t)node * FF);

    float acc[HH];
    #pragma unroll
    for (int j = 0; j < HH; j++) acc[j] = 0.0f;

    // lane li covers features k = r*32 + li*4 + c,  r=0..3, c=0..3
    #pragma unroll
    for (int r = 0; r < 4; r++) {
        float4 xv = xp[r * 8 + li];
        int kb = r * 32 + li * 4;
        #pragma unroll
        for (int c = 0; c < 4; c++) {
            float xs = (c == 0) ? xv.x : (c == 1) ? xv.y : (c == 2) ? xv.z : xv.w;
            const float4* wr = (const float4*)&w1s[(kb + c) * HH];
            #pragma unroll
            for (int q = 0; q < 4; q++) {
                float4 w = wr[q];
                acc[4*q+0] += xs * w.x;
                acc[4*q+1] += xs * w.y;
                acc[4*q+2] += xs * w.z;
                acc[4*q+3] += xs * w.w;
            }
        }
    }

    // reduce across the 8 lanes of this node's group (xor 1,2,4 stays in-group)
    #pragma unroll
    for (int off = 1; off < 8; off <<= 1) {
        #pragma unroll
        for (int j = 0; j < HH; j++)
            acc[j] += __shfl_xor_sync(0xffffffffu, acc[j], off);
    }

    // lanes 0..3 of each group write one float4 each (to both buffers)
    if (li < 4) {
        float di = g_dinv[node];
        float4 v = make_float4(acc[4*li+0]*di, acc[4*li+1]*di,
                               acc[4*li+2]*di, acc[4*li+3]*di);
        ((float4*)&g_tmps[(size_t)node * HH])[li] = v;
        ((float4*)&g_agg1[(size_t)node * HH])[li] = v;   // self-loop init
    }
}

__device__ __forceinline__ void red_v4(float* p, float4 v) {
    asm volatile("red.global.add.v4.f32 [%0], {%1,%2,%3,%4};"
                 :: "l"(p), "f"(v.x), "f"(v.y), "f"(v.z), "f"(v.w) : "memory");
}

// edge aggregation: out[dst] += in[src] (16-wide). 2 edges/thread, int2 idx loads.
template <int PASS>
__global__ void k_agg(const int* __restrict__ src, const int* __restrict__ dst, int ne) {
    int t = blockIdx.x * blockDim.x + threadIdx.x;
    int e0 = t * 2;
    if (e0 >= ne) return;
    const float* in = (PASS == 0) ? g_tmps : g_h2s;
    float* outp     = (PASS == 0) ? g_agg1 : g_agg2;

    if (e0 + 1 < ne) {
        int2 s2 = ((const int2*)src)[t];
        int2 d2 = ((const int2*)dst)[t];
        const float4* ip0 = (const float4*)(in + (size_t)s2.x * HH);
        const float4* ip1 = (const float4*)(in + (size_t)s2.y * HH);
        float4 a0 = ip0[0], a1 = ip0[1], a2 = ip0[2], a3 = ip0[3];
        float4 b0 = ip1[0], b1 = ip1[1], b2 = ip1[2], b3 = ip1[3];
        float* op0 = outp + (size_t)d2.x * HH;
        float* op1 = outp + (size_t)d2.y * HH;
        red_v4(op0 + 0, a0);  red_v4(op0 + 4, a1);
        red_v4(op0 + 8, a2);  red_v4(op0 + 12, a3);
        red_v4(op1 + 0, b0);  red_v4(op1 + 4, b1);
        red_v4(op1 + 8, b2);  red_v4(op1 + 12, b3);
    } else {
        int s = src[e0], d = dst[e0];
        const float4* ip = (const float4*)(in + (size_t)s * HH);
        float4 a0 = ip[0], a1 = ip[1], a2 = ip[2], a3 = ip[3];
        float* op = outp + (size_t)d * HH;
        red_v4(op + 0, a0);  red_v4(op + 4, a1);
        red_v4(op + 8, a2);  red_v4(op + 12, a3);
    }
}

// h = relu(dinv*agg1 + b1)  (agg1 already includes self-loop term), BN stats
__global__ void k_post1(const float* __restrict__ b1, int n) {
    __shared__ float sb1[HH];
    __shared__ float sred[2 * HH];
    int t = threadIdx.x;
    if (t < HH) sb1[t] = b1[t];
    if (t < 2 * HH) sred[t] = 0.0f;
    __syncthreads();

    float ls[HH], lq[HH];
    #pragma unroll
    for (int j = 0; j < HH; j++) { ls[j] = 0.0f; lq[j] = 0.0f; }

    for (int node = blockIdx.x * blockDim.x + t; node < n;
         node += gridDim.x * blockDim.x) {
        float di = g_dinv[node];
        const float4* ap = (const float4*)&g_agg1[(size_t)node * HH];
        float4* hp = (float4*)&g_h[(size_t)node * HH];
        #pragma unroll
        for (int q = 0; q < 4; q++) {
            float4 a = ap[q];
            float h0 = fmaxf(di * a.x + sb1[4*q+0], 0.0f);
            float h1 = fmaxf(di * a.y + sb1[4*q+1], 0.0f);
            float h2 = fmaxf(di * a.z + sb1[4*q+2], 0.0f);
            float h3 = fmaxf(di * a.w + sb1[4*q+3], 0.0f);
            hp[q] = make_float4(h0, h1, h2, h3);
            ls[4*q+0] += h0; lq[4*q+0] += h0 * h0;
            ls[4*q+1] += h1; lq[4*q+1] += h1 * h1;
            ls[4*q+2] += h2; lq[4*q+2] += h2 * h2;
            ls[4*q+3] += h3; lq[4*q+3] += h3 * h3;
        }
    }

    #pragma unroll
    for (int j = 0; j < HH; j++) {
        #pragma unroll
        for (int off = 16; off; off >>= 1) {
            ls[j] += __shfl_xor_sync(0xffffffffu, ls[j], off);
            lq[j] += __shfl_xor_sync(0xffffffffu, lq[j], off);
        }
    }
    if ((t & 31) == 0) {
        #pragma unroll
        for (int j = 0; j < HH; j++) {
            atomicAdd(&sred[j], ls[j]);
            atomicAdd(&sred[HH + j], lq[j]);
        }
    }
    __syncthreads();
    if (t < 2 * HH) atomicAdd(&g_stats[t], sred[t]);
}

__global__ void k_bnfin(const float* __restrict__ gamma,
                        const float* __restrict__ beta, float invN) {
    int j = threadIdx.x;
    if (j < HH) {
        float mean = g_stats[j] * invN;
        float var  = g_stats[HH + j] * invN - mean * mean;
        float sc   = gamma[j] * rsqrtf(var + BN_EPS);
        g_scale[j] = sc;
        g_shift[j] = beta[j] - mean * sc;
    }
}

// BN apply + 10 residual hops + dinv pre-scale -> g_h2s AND g_agg2 (self-loop init)
__global__ void k_hops(const float* __restrict__ Wl, const float* __restrict__ bl, int n) {
    __shared__ float swl[HH * HH];
    __shared__ float sbl[HH], ssc[HH], ssh[HH];
    int t = threadIdx.x;
    if (t < HH * HH) swl[t] = Wl[t];
    if (t < HH) { sbl[t] = bl[t]; ssc[t] = g_scale[t]; ssh[t] = g_shift[t]; }
    __syncthreads();

    int node = blockIdx.x * blockDim.x + t;
    if (node >= n) return;

    float v[HH];
    const float4* hp = (const float4*)&g_h[(size_t)node * HH];
    #pragma unroll
    for (int q = 0; q < 4; q++) {
        float4 a = hp[q];
        v[4*q+0] = a.x; v[4*q+1] = a.y; v[4*q+2] = a.z; v[4*q+3] = a.w;
    }
    #pragma unroll
    for (int j = 0; j < HH; j++) v[j] = v[j] * ssc[j] + ssh[j];

    #pragma unroll 1
    for (int it = 0; it < 10; it++) {
        float acc[HH];
        #pragma unroll
        for (int j = 0; j < HH; j++) acc[j] = sbl[j];
        #pragma unroll
        for (int k = 0; k < HH; k++) {
            float hk = v[k];
            const float4* wr = (const float4*)&swl[k * HH];
            #pragma unroll
            for (int q = 0; q < 4; q++) {
                float4 w = wr[q];
                acc[4*q+0] += hk * w.x;
                acc[4*q+1] += hk * w.y;
                acc[4*q+2] += hk * w.z;
                acc[4*q+3] += hk * w.w;
            }
        }
        #pragma unroll
        for (int j = 0; j < HH; j++)
            v[j] = ALPHA * fmaxf(acc[j], 0.0f) + (1.0f - ALPHA) * v[j];
    }

    float di = g_dinv[node];
    float4* op = (float4*)&g_h2s[(size_t)node * HH];
    float4* op2 = (float4*)&g_agg2[(size_t)node * HH];
    #pragma unroll
    for (int q = 0; q < 4; q++) {
        float4 w = make_float4(v[4*q+0]*di, v[4*q+1]*di, v[4*q+2]*di, v[4*q+3]*di);
        op[q] = w;
        op2[q] = w;          // self-loop init
    }
}

// v = dinv*agg2; out = log_softmax(v @ W2 + b2)
__global__ void k_final(const float* __restrict__ W2, const float* __restrict__ b2,
                        float* __restrict__ out, int n) {
    __shared__ float sw2[HH * CC];
    __shared__ float sb2[CC];
    int t = threadIdx.x;
    for (int i = t; i < HH * CC; i += blockDim.x) sw2[i] = W2[i];
    if (t < CC) sb2[t] = b2[t];
    __syncthreads();

    int node = blockIdx.x * blockDim.x + t;
    if (node >= n) return;

    float di = g_dinv[node];
    float v[HH];
    const float4* ap = (const float4*)&g_agg2[(size_t)node * HH];
    #pragma unroll
    for (int q = 0; q < 4; q++) {
        float4 a = ap[q];
        v[4*q+0] = di * a.x;
        v[4*q+1] = di * a.y;
        v[4*q+2] = di * a.z;
        v[4*q+3] = di * a.w;
    }

    float o[CC];
    #pragma unroll
    for (int j = 0; j < CC; j++) o[j] = sb2[j];
    #pragma unroll
    for (int k = 0; k < HH; k++) {
        float hk = v[k];
        const float4* wr = (const float4*)&sw2[k * CC];
        #pragma unroll
        for (int q = 0; q < CC / 4; q++) {
            float4 w = wr[q];
            o[4*q+0] += hk * w.x;
            o[4*q+1] += hk * w.y;
            o[4*q+2] += hk * w.z;
            o[4*q+3] += hk * w.w;
        }
    }

    float m = o[0];
    #pragma unroll
    for (int j = 1; j < CC; j++) m = fmaxf(m, o[j]);
    float s = 0.0f;
    #pragma unroll
    for (int j = 0; j < CC; j++) s += expf(o[j] - m);
    float lse = m + logf(s);

    float4* op4 = (float4*)&out[(size_t)node * CC];
    #pragma unroll
    for (int q = 0; q < CC / 4; q++)
        op4[q] = make_float4(o[4*q+0]-lse, o[4*q+1]-lse, o[4*q+2]-lse, o[4*q+3]-lse);
}

// ---------------- launch ----------------
extern "C" void kernel_launch(void* const* d_in, const int* in_sizes, int n_in,
                              void* d_out, int out_size) {
    const float* x     = (const float*)d_in[0];
    const int*   src   = (const int*)d_in[1];
    const int*   dst   = (const int*)d_in[2];
    const float* W1    = (const float*)d_in[3];
    const float* b1    = (const float*)d_in[4];
    const float* gamma = (const float*)d_in[5];
    const float* beta  = (const float*)d_in[6];
    const float* Wl    = (const float*)d_in[7];
    const float* bl    = (const float*)d_in[8];
    const float* W2    = (const float*)d_in[9];
    const float* b2    = (const float*)d_in[10];
    float* out = (float*)d_out;

    int n  = in_sizes[0] / FF;
    int ne = in_sizes[1];
    if (n > NN) n = NN;

    int nb256 = (n + 255) / 256;
    int eb256 = (ne + 255) / 256;
    int eb2   = (ne / 2 + 255) / 256 + 1;     // 2 edges per thread

    k_init<<<nb256, 256>>>(n);
    k_deg<<<eb256, 256>>>(dst, ne);
    k_dinv<<<nb256, 256>>>(n);
    k_mm1<<<(n + 31) / 32, 256>>>(x, W1, n);
    k_agg<0><<<eb2, 256>>>(src, dst, ne);
    k_post1<<<256, 256>>>(b1, n);
    k_bnfin<<<1, 32>>>(gamma, beta, 1.0f / (float)n);
    k_hops<<<nb256, 256>>>(Wl, bl, n);
    k_agg<1><<<eb2, 256>>>(src, dst, ne);
    k_final<<<nb256, 256>>>(W2, b2, out, n);
}

// round 3
// speedup vs baseline: 2.0562x; 2.0562x over previous
#include <cuda_runtime.h>
#include <math.h>

#define NN 100000
#define EE 3200000
#define FF 128
#define HH 16
#define CC 40
#define ALPHA 0.1f
#define BN_EPS 1e-5f
#define SB 512                 // scan block size

// ---------------- scratch (device globals; no allocation) ----------------
__device__ __align__(16) float g_tmps[NN * HH];   // (x@W1) * dinv  (src-side, conv1)
__device__ __align__(16) float g_agg1[NN * HH];   // conv1 sum, init = self-loop term
__device__ __align__(16) float g_agg2[NN * HH];   // conv2 sum, init = self-loop term
__device__ __align__(16) float g_h[NN * HH];      // post-relu hidden
__device__ __align__(16) float g_h2s[NN * HH];    // post-hops hidden * dinv (src-side)
__device__ float g_dinv[NN];
__device__ float g_stats[2 * HH];
__device__ float g_scale[HH];
__device__ float g_shift[HH];
// CSR machinery
__device__ int g_cnt[NN];          // in-degree (no self loop)
__device__ int g_off[NN];          // CSR row start
__device__ int g_cur[NN];          // fill cursor
__device__ int g_btot[256];        // scan block totals
__device__ int g_bpre[256];        // scan block prefixes
__device__ int g_csr[EE];          // src indices grouped by dst

// ---------------- setup kernels ----------------

__global__ void k_init(int n) {
    int i = blockIdx.x * blockDim.x + threadIdx.x;
    if (i < n) g_cnt[i] = 0;
    if (i < 2 * HH) g_stats[i] = 0.0f;
}

__global__ void k_cnt(const int* __restrict__ dst, int ne) {
    int e = blockIdx.x * blockDim.x + threadIdx.x;
    if (e < ne) atomicAdd(&g_cnt[dst[e]], 1);
}

__global__ void k_dinv(int n) {
    int i = blockIdx.x * blockDim.x + threadIdx.x;
    if (i < n) g_dinv[i] = rsqrtf((float)(g_cnt[i] + 1));   // +1 self loop
}

// ---- 3-kernel exclusive scan of g_cnt -> g_off ----
__global__ void k_scan1(int n) {
    __shared__ int wsum[SB / 32];
    int t = threadIdx.x, b = blockIdx.x;
    int i = b * SB + t;
    int v = (i < n) ? g_cnt[i] : 0;
    int x = v;
    #pragma unroll
    for (int off = 1; off < 32; off <<= 1) {
        int y = __shfl_up_sync(0xffffffffu, x, off);
        if ((t & 31) >= off) x += y;
    }
    if ((t & 31) == 31) wsum[t >> 5] = x;
    __syncthreads();
    if (t < SB / 32) {
        int w = wsum[t];
        #pragma unroll
        for (int off = 1; off < SB / 32; off <<= 1) {
            int y = __shfl_up_sync((1u << (SB / 32)) - 1u, w, off);
            if (t >= off) w += y;
        }
        wsum[t] = w;
    }
    __syncthreads();
    int prefix = (t >= 32) ? wsum[(t >> 5) - 1] : 0;
    if (i < n) g_off[i] = prefix + x - v;        // block-local exclusive
    if (t == SB - 1) g_btot[b] = prefix + x;     // block total
}

__global__ void k_scan2(int nb) {   // 1 block, 256 threads; nb <= 256
    __shared__ int wsum[8];
    int t = threadIdx.x;
    int v = (t < nb) ? g_btot[t] : 0;
    int x = v;
    #pragma unroll
    for (int off = 1; off < 32; off <<= 1) {
        int y = __shfl_up_sync(0xffffffffu, x, off);
        if ((t & 31) >= off) x += y;
    }
    if ((t & 31) == 31) wsum[t >> 5] = x;
    __syncthreads();
    if (t < 8) {
        int w = wsum[t];
        #pragma unroll
        for (int off = 1; off < 8; off <<= 1) {
            int y = __shfl_up_sync(0xffu, w, off);
            if (t >= off) w += y;
        }
        wsum[t] = w;
    }
    __syncthreads();
    int prefix = (t >= 32) ? wsum[(t >> 5) - 1] : 0;
    if (t < nb) g_bpre[t] = prefix + x - v;      // exclusive block prefix
}

__global__ void k_scan3(int n) {
    int i = blockIdx.x * blockDim.x + threadIdx.x;
    if (i < n) {
        int o = g_off[i] + g_bpre[i / SB];
        g_off[i] = o;
        g_cur[i] = o;
    }
}

__global__ void k_fill(const int* __restrict__ src, const int* __restrict__ dst, int ne) {
    int e = blockIdx.x * blockDim.x + threadIdx.x;
    if (e < ne) {
        int d = dst[e];
        int p = atomicAdd(&g_cur[d], 1);
        g_csr[p] = src[e];
    }
}

// ---------------- compute kernels ----------------

// x[N,128] @ W1[128,16] * dinv -> g_tmps AND g_agg1 (self-loop init).
// 256 threads: 64-node smem tile, 4 threads per node, 4 outputs each. No shuffles.
#define TILE 64
__global__ void __launch_bounds__(256) k_mm1(const float* __restrict__ x,
                                             const float* __restrict__ W1, int n) {
    __shared__ float4 xs[TILE][33];      // row = 33 float4 (132 floats) -> conflict-free
    __shared__ float w1s[FF * HH];       // 8KB
    int t = threadIdx.x;
    int base = blockIdx.x * TILE;

    #pragma unroll
    for (int i = t; i < FF * HH; i += 256) w1s[i] = W1[i];

    const float4* xg = (const float4*)x;
    #pragma unroll
    for (int i = t; i < TILE * 32; i += 256) {
        int r = i >> 5, c = i & 31;
        float4 v = make_float4(0.f, 0.f, 0.f, 0.f);
        if (base + r < n) v = xg[(size_t)(base + r) * 32 + c];
        xs[r][c] = v;
    }
    __syncthreads();

    int ni = t >> 2;                 // node in tile (0..63)
    int jg = t & 3;                  // output quad (0..3)
    int node = base + ni;

    const float* xrow = (const float*)&xs[ni][0];
    float a0 = 0.f, a1 = 0.f, a2 = 0.f, a3 = 0.f;
    #pragma unroll 8
    for (int k = 0; k < FF; k++) {
        float xv = xrow[k];
        float4 w = *(const float4*)&w1s[k * HH + jg * 4];
        a0 += xv * w.x; a1 += xv * w.y; a2 += xv * w.z; a3 += xv * w.w;
    }

    if (node < n) {
        float di = g_dinv[node];
        float4 v = make_float4(a0 * di, a1 * di, a2 * di, a3 * di);
        ((float4*)&g_tmps[(size_t)node * HH])[jg] = v;
        ((float4*)&g_agg1[(size_t)node * HH])[jg] = v;   // self-loop init
    }
}

// CSR gather aggregation: one warp per dst node. agg buffer already holds self term.
template <int PASS>
__global__ void k_agg_csr(int n) {
    int warp = (blockIdx.x * blockDim.x + threadIdx.x) >> 5;
    if (warp >= n) return;
    const float* in = (PASS == 0) ? g_tmps : g_h2s;
    float* outp     = (PASS == 0) ? g_agg1 : g_agg2;

    int lane = threadIdx.x & 31;
    int slot = lane >> 2;            // 0..7 edge slots
    int c    = lane & 3;             // float4 within row
    int beg = g_off[warp];
    int cnt = g_cnt[warp];

    float4 acc = make_float4(0.f, 0.f, 0.f, 0.f);
    for (int j = slot; j < cnt; j += 8) {
        int s = g_csr[beg + j];
        float4 v = ((const float4*)(in + (size_t)s * HH))[c];
        acc.x += v.x; acc.y += v.y; acc.z += v.z; acc.w += v.w;
    }
    #pragma unroll
    for (int off = 4; off < 32; off <<= 1) {
        acc.x += __shfl_xor_sync(0xffffffffu, acc.x, off);
        acc.y += __shfl_xor_sync(0xffffffffu, acc.y, off);
        acc.z += __shfl_xor_sync(0xffffffffu, acc.z, off);
        acc.w += __shfl_xor_sync(0xffffffffu, acc.w, off);
    }
    if (lane < 4) {                  // lane == c here
        float4* op = (float4*)(outp + (size_t)warp * HH);
        float4 cur = op[lane];
        op[lane] = make_float4(cur.x + acc.x, cur.y + acc.y,
                               cur.z + acc.z, cur.w + acc.w);
    }
}

// h = relu(dinv*agg1 + b1); BN stats
__global__ void k_post1(const float* __restrict__ b1, int n) {
    __shared__ float sb1[HH];
    __shared__ float sred[2 * HH];
    int t = threadIdx.x;
    if (t < HH) sb1[t] = b1[t];
    if (t < 2 * HH) sred[t] = 0.0f;
    __syncthreads();

    float ls[HH], lq[HH];
    #pragma unroll
    for (int j = 0; j < HH; j++) { ls[j] = 0.0f; lq[j] = 0.0f; }

    for (int node = blockIdx.x * blockDim.x + t; node < n;
         node += gridDim.x * blockDim.x) {
        float di = g_dinv[node];
        const float4* ap = (const float4*)&g_agg1[(size_t)node * HH];
        float4* hp = (float4*)&g_h[(size_t)node * HH];
        #pragma unroll
        for (int q = 0; q < 4; q++) {
            float4 a = ap[q];
            float h0 = fmaxf(di * a.x + sb1[4*q+0], 0.0f);
            float h1 = fmaxf(di * a.y + sb1[4*q+1], 0.0f);
            float h2 = fmaxf(di * a.z + sb1[4*q+2], 0.0f);
            float h3 = fmaxf(di * a.w + sb1[4*q+3], 0.0f);
            hp[q] = make_float4(h0, h1, h2, h3);
            ls[4*q+0] += h0; lq[4*q+0] += h0 * h0;
            ls[4*q+1] += h1; lq[4*q+1] += h1 * h1;
            ls[4*q+2] += h2; lq[4*q+2] += h2 * h2;
            ls[4*q+3] += h3; lq[4*q+3] += h3 * h3;
        }
    }

    #pragma unroll
    for (int j = 0; j < HH; j++) {
        #pragma unroll
        for (int off = 16; off; off >>= 1) {
            ls[j] += __shfl_xor_sync(0xffffffffu, ls[j], off);
            lq[j] += __shfl_xor_sync(0xffffffffu, lq[j], off);
        }
    }
    if ((t & 31) == 0) {
        #pragma unroll
        for (int j = 0; j < HH; j++) {
            atomicAdd(&sred[j], ls[j]);
            atomicAdd(&sred[HH + j], lq[j]);
        }
    }
    __syncthreads();
    if (t < 2 * HH) atomicAdd(&g_stats[t], sred[t]);
}

__global__ void k_bnfin(const float* __restrict__ gamma,
                        const float* __restrict__ beta, float invN) {
    int j = threadIdx.x;
    if (j < HH) {
        float mean = g_stats[j] * invN;
        float var  = g_stats[HH + j] * invN - mean * mean;
        float sc   = gamma[j] * rsqrtf(var + BN_EPS);
        g_scale[j] = sc;
        g_shift[j] = beta[j] - mean * sc;
    }
}

// BN apply + 10 residual hops + dinv pre-scale -> g_h2s AND g_agg2 (self-loop init)
__global__ void k_hops(const float* __restrict__ Wl, const float* __restrict__ bl, int n) {
    __shared__ float swl[HH * HH];
    __shared__ float sbl[HH], ssc[HH], ssh[HH];
    int t = threadIdx.x;
    if (t < HH * HH) swl[t] = Wl[t];
    if (t < HH) { sbl[t] = bl[t]; ssc[t] = g_scale[t]; ssh[t] = g_shift[t]; }
    __syncthreads();

    int node = blockIdx.x * blockDim.x + t;
    if (node >= n) return;

    float v[HH];
    const float4* hp = (const float4*)&g_h[(size_t)node * HH];
    #pragma unroll
    for (int q = 0; q < 4; q++) {
        float4 a = hp[q];
        v[4*q+0] = a.x; v[4*q+1] = a.y; v[4*q+2] = a.z; v[4*q+3] = a.w;
    }
    #pragma unroll
    for (int j = 0; j < HH; j++) v[j] = v[j] * ssc[j] + ssh[j];

    #pragma unroll 1
    for (int it = 0; it < 10; it++) {
        float acc[HH];
        #pragma unroll
        for (int j = 0; j < HH; j++) acc[j] = sbl[j];
        #pragma unroll
        for (int k = 0; k < HH; k++) {
            float hk = v[k];
            const float4* wr = (const float4*)&swl[k * HH];
            #pragma unroll
            for (int q = 0; q < 4; q++) {
                float4 w = wr[q];
                acc[4*q+0] += hk * w.x;
                acc[4*q+1] += hk * w.y;
                acc[4*q+2] += hk * w.z;
                acc[4*q+3] += hk * w.w;
            }
        }
        #pragma unroll
        for (int j = 0; j < HH; j++)
            v[j] = ALPHA * fmaxf(acc[j], 0.0f) + (1.0f - ALPHA) * v[j];
    }

    float di = g_dinv[node];
    float4* op = (float4*)&g_h2s[(size_t)node * HH];
    float4* op2 = (float4*)&g_agg2[(size_t)node * HH];
    #pragma unroll
    for (int q = 0; q < 4; q++) {
        float4 w = make_float4(v[4*q+0]*di, v[4*q+1]*di, v[4*q+2]*di, v[4*q+3]*di);
        op[q] = w;
        op2[q] = w;          // self-loop init
    }
}

// v = dinv*agg2; out = log_softmax(v @ W2 + b2)
__global__ void k_final(const float* __restrict__ W2, const float* __restrict__ b2,
                        float* __restrict__ out, int n) {
    __shared__ float sw2[HH * CC];
    __shared__ float sb2[CC];
    int t = threadIdx.x;
    for (int i = t; i < HH * CC; i += blockDim.x) sw2[i] = W2[i];
    if (t < CC) sb2[t] = b2[t];
    __syncthreads();

    int node = blockIdx.x * blockDim.x + t;
    if (node >= n) return;

    float di = g_dinv[node];
    float v[HH];
    const float4* ap = (const float4*)&g_agg2[(size_t)node * HH];
    #pragma unroll
    for (int q = 0; q < 4; q++) {
        float4 a = ap[q];
        v[4*q+0] = di * a.x;
        v[4*q+1] = di * a.y;
        v[4*q+2] = di * a.z;
        v[4*q+3] = di * a.w;
    }

    float o[CC];
    #pragma unroll
    for (int j = 0; j < CC; j++) o[j] = sb2[j];
    #pragma unroll
    for (int k = 0; k < HH; k++) {
        float hk = v[k];
        const float4* wr = (const float4*)&sw2[k * CC];
        #pragma unroll
        for (int q = 0; q < CC / 4; q++) {
            float4 w = wr[q];
            o[4*q+0] += hk * w.x;
            o[4*q+1] += hk * w.y;
            o[4*q+2] += hk * w.z;
            o[4*q+3] += hk * w.w;
        }
    }

    float m = o[0];
    #pragma unroll
    for (int j = 1; j < CC; j++) m = fmaxf(m, o[j]);
    float s = 0.0f;
    #pragma unroll
    for (int j = 0; j < CC; j++) s += expf(o[j] - m);
    float lse = m + logf(s);

    float4* op4 = (float4*)&out[(size_t)node * CC];
    #pragma unroll
    for (int q = 0; q < CC / 4; q++)
        op4[q] = make_float4(o[4*q+0]-lse, o[4*q+1]-lse, o[4*q+2]-lse, o[4*q+3]-lse);
}

// ---------------- launch ----------------
extern "C" void kernel_launch(void* const* d_in, const int* in_sizes, int n_in,
                              void* d_out, int out_size) {
    const float* x     = (const float*)d_in[0];
    const int*   src   = (const int*)d_in[1];
    const int*   dst   = (const int*)d_in[2];
    const float* W1    = (const float*)d_in[3];
    const float* b1    = (const float*)d_in[4];
    const float* gamma = (const float*)d_in[5];
    const float* beta  = (const float*)d_in[6];
    const float* Wl    = (const float*)d_in[7];
    const float* bl    = (const float*)d_in[8];
    const float* W2    = (const float*)d_in[9];
    const float* b2    = (const float*)d_in[10];
    float* out = (float*)d_out;

    int n  = in_sizes[0] / FF;
    int ne = in_sizes[1];
    if (n > NN) n = NN;
    if (ne > EE) ne = EE;

    int nb256 = (n + 255) / 256;
    int eb256 = (ne + 255) / 256;
    int nscan = (n + SB - 1) / SB;           // <= 256 for n <= 131072
    int aggblocks = (n * 32 + 255) / 256;    // warp per node

    k_init<<<nb256, 256>>>(n);
    k_cnt<<<eb256, 256>>>(dst, ne);
    k_dinv<<<nb256, 256>>>(n);
    k_scan1<<<nscan, SB>>>(n);
    k_scan2<<<1, 256>>>(nscan);
    k_scan3<<<nb256, 256>>>(n);
    k_fill<<<eb256, 256>>>(src, dst, ne);
    k_mm1<<<(n + TILE - 1) / TILE, 256>>>(x, W1, n);
    k_agg_csr<0><<<aggblocks, 256>>>(n);
    k_post1<<<256, 256>>>(b1, n);
    k_bnfin<<<1, 32>>>(gamma, beta, 1.0f / (float)n);
    k_hops<<<nb256, 256>>>(Wl, bl, n);
    k_agg_csr<1><<<aggblocks, 256>>>(n);
    k_final<<<nb256, 256>>>(W2, b2, out, n);
}